// round 10
// baseline (speedup 1.0000x reference)
#include <cuda_runtime.h>
#include <cuda_fp16.h>
#include <cstdint>

#define NN 320
#define DD 64
#define PB 7
#define NBLK 143     // 143*7 = 1001 datasets exactly
#define CH 10        // staged rows per chunk
#define NCH 32       // 32*10 = 320 rows
#define STRIDE 328   // half2 per staged row (padded: 1312B % 128 = 32)

// Precomputed, perm-independent state.
__device__ __align__(16) __half2 d_PD[NN*NN]; // (Delta, Dp) packed per element
__device__ float d_RD[NN];      // row sums of Delta (fp32)
__device__ float d_rowC[NN];    // per-row sum of Dp over b>a (fp32)
__device__ float d_sn[NN];      // squared norms
__device__ float d_qd[NN];      // X1 . x_a = row sum of Gram

__device__ __forceinline__ float warpRed(float v){
#pragma unroll
    for (int o = 16; o > 0; o >>= 1) v += __shfl_down_sync(0xffffffffu, v, o);
    return v;
}
__device__ __forceinline__ __half2 u2h(unsigned u){
    return *reinterpret_cast<__half2*>(&u);
}
__device__ __forceinline__ float lowf(unsigned u){
    return __half2float(__low2half(u2h(u)));
}
__device__ __forceinline__ void cpa16(uint32_t s, const void* g){
    asm volatile("cp.async.cg.shared.global [%0], [%1], 16;\n" :: "r"(s), "l"(g));
}

// Fused precompute: one block per row a, thread = column b.
__global__ void __launch_bounds__(NN) k_pre(const float* __restrict__ x){
    __shared__ float xa[DD];
    __shared__ float sa_sh;
    __shared__ float red[3][10];
    int a = blockIdx.x, b = threadIdx.x;
    if (b < DD) xa[b] = x[a*DD + b];
    __syncthreads();
    const float4* xb = reinterpret_cast<const float4*>(x + b*DD);
    float g = 0.f, nb = 0.f;
#pragma unroll
    for (int i = 0; i < DD/4; i++){
        float4 v = xb[i];
        g  += xa[4*i]*v.x + xa[4*i+1]*v.y + xa[4*i+2]*v.z + xa[4*i+3]*v.w;
        nb += v.x*v.x + v.y*v.y + v.z*v.z + v.w*v.w;
    }
    if (b == a){ sa_sh = nb; d_sn[a] = nb; }
    __syncthreads();
    float sa = sa_sh;
    float dp = sqrtf(fmaxf(sa + nb - 2.f*g, 0.f));
    float dm = sqrtf(fmaxf(sa + nb + 2.f*g, 0.f));
    float dl = dm - dp;
    d_PD[a*NN + b] = __floats2half2_rn(dl, dp);

    int w = b >> 5, l = b & 31;
    float v0 = warpRed(dl);
    float v1 = warpRed(b > a ? dp : 0.f);
    float v2 = warpRed(g);
    if (l == 0){ red[0][w] = v0; red[1][w] = v1; red[2][w] = v2; }
    __syncthreads();
    if (b == 0){
        float s0 = 0.f, s1 = 0.f, s2 = 0.f;
#pragma unroll
        for (int i = 0; i < 10; i++){ s0 += red[0][i]; s1 += red[1][i]; s2 += red[2][i]; }
        d_RD[a]   = s0;
        d_rowC[a] = s1;
        d_qd[a]   = s2;
    }
}

// Main: one block per 7 datasets. Dense streaming through cp.async-staged smem.
__global__ void __launch_bounds__(NN) k_main(const float* __restrict__ x,
                                             const int* __restrict__ ptype,
                                             const int* __restrict__ perms,
                                             float* __restrict__ out){
    __shared__ __align__(16) __half2 wts[NN][8];      // (beta, chi) per (index, perm); slot 7 pad
    __shared__ __align__(16) __half2 stage[2*CH*STRIDE];
    __shared__ float sZp[5][PB][DD];                  // s-vector slice partials
    __shared__ float red[PB*5+3][10];
    __shared__ float red2[PB][2];

    int t = threadIdx.x, bid = blockIdx.x;
    int w = t >> 5, l = t & 31;
    int fn = (ptype[t] == 0);

    // pad slot 7 (read as part of uint4, never used)
    wts[t][7] = __floats2half2_rn(0.f, 0.f);

    // Build masks: thread t scatters to its image index a (bijection => full coverage).
#pragma unroll
    for (int pp = 0; pp < PB; pp++){
        int pi = bid*PB + pp;                 // dataset 0 = identity
        int a  = (pi == 0) ? t : perms[(pi-1)*NN + t];
        int fa = (ptype[a] == 0);
        int u  = (a != t) && fn && fa;
        wts[a][pp] = __floats2half2_rn((float)u, (float)fn);
    }
    __syncthreads();

    // ---- Prologue: prefetch chunks 0,1 ----
    uint32_t stageBase = (uint32_t)__cvta_generic_to_shared(stage);
#pragma unroll
    for (int k = 0; k < 3; k++){
        int idx = t + 320*k;                  // 800 quads per chunk
        if (idx < CH*80){
            int r = idx / 80, q = idx - r*80;
            cpa16(stageBase + (uint32_t)((r*STRIDE + 4*q)*4),
                  d_PD + (size_t)r*NN + 4*q);
        }
    }
    asm volatile("cp.async.commit_group;" ::: "memory");
#pragma unroll
    for (int k = 0; k < 3; k++){
        int idx = t + 320*k;
        if (idx < CH*80){
            int r = idx / 80, q = idx - r*80;
            cpa16(stageBase + (uint32_t)(((CH + r)*STRIDE + 4*q)*4),
                  d_PD + (size_t)(CH + r)*NN + 4*q);
        }
    }
    asm volatile("cp.async.commit_group;" ::: "memory");

    // ---- s_p = sum_a beta_p[a] * x[a,:] (fp32 exact) while prefetches land ----
    {
        int d = t & 63, g5 = t >> 6;          // 5 row-slices of 64 dims
        float sacc[PB];
#pragma unroll
        for (int p = 0; p < PB; p++) sacc[p] = 0.f;
        const float* xp = x + (size_t)g5*DD + d;
        int row = g5;
#pragma unroll 4
        for (int i2 = 0; i2 < 64; i2++){
            float xv = *xp;
            uint4 w0 = *reinterpret_cast<const uint4*>(&wts[row][0]);
            uint4 w1 = *reinterpret_cast<const uint4*>(&wts[row][4]);
            sacc[0] = fmaf(lowf(w0.x), xv, sacc[0]);
            sacc[1] = fmaf(lowf(w0.y), xv, sacc[1]);
            sacc[2] = fmaf(lowf(w0.z), xv, sacc[2]);
            sacc[3] = fmaf(lowf(w0.w), xv, sacc[3]);
            sacc[4] = fmaf(lowf(w1.x), xv, sacc[4]);
            sacc[5] = fmaf(lowf(w1.y), xv, sacc[5]);
            sacc[6] = fmaf(lowf(w1.z), xv, sacc[6]);
            xp += 5*DD; row += 5;
        }
#pragma unroll
        for (int p = 0; p < PB; p++) sZp[g5][p][t & 63] = sacc[p];
    }

    // ---- Main staged loop: 4 row-slices x 80 quad-columns ----
    int g = t % 80, sl = t / 80;
    const __half2 hz = __float2half2_rn(0.f);
    __half2 acc[PB][4];
#pragma unroll
    for (int p = 0; p < PB; p++)
#pragma unroll
        for (int c = 0; c < 4; c++) acc[p][c] = hz;
    float bb[PB], bx[PB], xx[PB];
#pragma unroll
    for (int p = 0; p < PB; p++){ bb[p] = 0.f; bx[p] = 0.f; xx[p] = 0.f; }

    for (int ch = 0; ch < NCH; ch++){
        if (ch == NCH-1) asm volatile("cp.async.wait_group 0;" ::: "memory");
        else             asm volatile("cp.async.wait_group 1;" ::: "memory");
        __syncthreads();

        const __half2* buf = stage + (ch & 1)*CH*STRIDE;
        for (int r = sl; r < CH; r += 4){
            int a = ch*CH + r;
            uint4 v4 = *reinterpret_cast<const uint4*>(buf + r*STRIDE + 4*g);
            uint4 w0 = *reinterpret_cast<const uint4*>(&wts[a][0]);
            uint4 w1 = *reinterpret_cast<const uint4*>(&wts[a][4]);
            __half2 val[4] = { u2h(v4.x), u2h(v4.y), u2h(v4.z), u2h(v4.w) };
            __half2 wp[PB] = { u2h(w0.x), u2h(w0.y), u2h(w0.z), u2h(w0.w),
                               u2h(w1.x), u2h(w1.y), u2h(w1.z) };
#pragma unroll
            for (int p = 0; p < PB; p++)
#pragma unroll
                for (int c = 0; c < 4; c++)
                    acc[p][c] = __hfma2(val[c], wp[p], acc[p][c]);
        }
        __syncthreads();

        if (ch + 2 < NCH){
#pragma unroll
            for (int k = 0; k < 3; k++){
                int idx = t + 320*k;
                if (idx < CH*80){
                    int r = idx / 80, q = idx - r*80;
                    cpa16(stageBase + (uint32_t)((((ch & 1)*CH + r)*STRIDE + 4*q)*4),
                          d_PD + (size_t)((ch+2)*CH + r)*NN + 4*q);
                }
            }
            asm volatile("cp.async.commit_group;" ::: "memory");
        }

        // promote half accumulators to fp32 every 8 chunks (<=24 rows/thread)
        if ((ch & 7) == 7 || ch == NCH-1){
#pragma unroll
            for (int c = 0; c < 4; c++){
                int col = 4*g + c;
                uint4 wc0 = *reinterpret_cast<const uint4*>(&wts[col][0]);
                uint4 wc1 = *reinterpret_cast<const uint4*>(&wts[col][4]);
                unsigned wcu[PB] = { wc0.x, wc0.y, wc0.z, wc0.w, wc1.x, wc1.y, wc1.z };
#pragma unroll
                for (int p = 0; p < PB; p++){
                    float2 f  = __half22float2(acc[p][c]);
                    float2 wv = __half22float2(u2h(wcu[p]));
                    bb[p] = fmaf(wv.x, f.x, bb[p]);   // beta-col * (beta-row . Delta)
                    bx[p] = fmaf(wv.y, f.x, bx[p]);   // chi-col  * (beta-row . Delta)
                    xx[p] = fmaf(wv.y, f.y, xx[p]);   // chi-col  * (chi-row . Dp)
                    acc[p][c] = hz;
                }
            }
        }
    }

    // ---- E1 reductions ----
    float rdv = d_RD[t], qdv = d_qd[t];
    uint4 wt0 = *reinterpret_cast<const uint4*>(&wts[t][0]);
    uint4 wt1 = *reinterpret_cast<const uint4*>(&wts[t][4]);
    unsigned wtu[PB] = { wt0.x, wt0.y, wt0.z, wt0.w, wt1.x, wt1.y, wt1.z };
#pragma unroll
    for (int p = 0; p < PB; p++){
        float b  = lowf(wtu[p]);
        float r0 = warpRed(bb[p]);
        float r1 = warpRed(bx[p]);
        float r2 = warpRed(xx[p]);
        float r3 = warpRed(b*rdv);   // LIN = beta . RD
        float r4 = warpRed(b*qdv);   // QS  = beta . qd
        if (l == 0){
            red[p*5+0][w] = r0; red[p*5+1][w] = r1; red[p*5+2][w] = r2;
            red[p*5+3][w] = r3; red[p*5+4][w] = r4;
        }
    }
    {
        float rc = warpRed(d_rowC[t]);   // -> C_Dp
        float rs = warpRed(d_sn[t]);     // -> S1
        float rq = warpRed(qdv);         // -> ||X1||^2
        if (l == 0){ red[PB*5+0][w] = rc; red[PB*5+1][w] = rs; red[PB*5+2][w] = rq; }
    }
    __syncthreads();

    // ---- E2: GG_p = ||s_p||^2 ----
    if (t < DD){
#pragma unroll
        for (int p = 0; p < PB; p++){
            float s = sZp[0][p][t] + sZp[1][p][t] + sZp[2][p][t]
                    + sZp[3][p][t] + sZp[4][p][t];
            float r = warpRed(s*s);
            if (l == 0) red2[p][w] = r;   // warps 0,1
        }
    }
    __syncthreads();

    // ---- Final combine: one thread per perm ----
    if (t < PB){
        float BB=0.f, BX=0.f, XX=0.f, LIN=0.f, QS=0.f, CDP=0.f, S1=0.f, X1SQ=0.f;
#pragma unroll
        for (int i3 = 0; i3 < 10; i3++){
            BB  += red[t*5+0][i3]; BX += red[t*5+1][i3]; XX += red[t*5+2][i3];
            LIN += red[t*5+3][i3]; QS += red[t*5+4][i3];
            CDP += red[PB*5+0][i3]; S1 += red[PB*5+1][i3]; X1SQ += red[PB*5+2][i3];
        }
        float GG = red2[t][0] + red2[t][1];
        const float M = 51040.f;                    // 320*319/2
        float Sv  = CDP + LIN + BB - 2.f*BX - XX;
        float Z2  = X1SQ - 4.f*QS + 4.f*GG;         // ||X1 - 2 sum_B x||^2
        float Sv2 = 320.f * S1 - Z2;
        out[bid*PB + t] = (Sv2 - Sv*Sv/M) / (M - 1.f);
    }
}

extern "C" void kernel_launch(void* const* d_in, const int* in_sizes, int n_in,
                              void* d_out, int out_size){
    const float* data  = (const float*)d_in[0];
    const int*   ptype = (const int*)d_in[3];
    const int*   perms = (const int*)d_in[4];
    float* out = (float*)d_out;
    k_pre <<<NN,   NN>>>(data);
    k_main<<<NBLK, NN>>>(data, ptype, perms, out);
}

// round 11
// speedup vs baseline: 1.0668x; 1.0668x over previous
#include <cuda_runtime.h>
#include <cuda_fp16.h>
#include <cstdint>

#define NN 320
#define DD 64
#define PB 7
#define NG 143       // 143*7 = 1001 datasets exactly
#define HROWS 160    // rows per half-block

// Precomputed, perm-independent state.
__device__ __align__(16) __half2 d_PD[NN*NN]; // (Delta, Dp) packed per element
__device__ float d_RD[NN];      // row sums of Delta (fp32)
__device__ float d_rowC[NN];    // per-row sum of Dp over b>a (fp32)
__device__ float d_sn[NN];      // squared norms
__device__ float d_qd[NN];      // X1 . x_a = row sum of Gram

// Cross-block scratch (static globals: no allocation).
__device__ float d_sc[NG][2][PB][5];   // partial BB,BX,XX,LIN,QS
__device__ float d_sZ[NG][2][PB][DD];  // partial s-vectors

__device__ __forceinline__ float warpRed(float v){
#pragma unroll
    for (int o = 16; o > 0; o >>= 1) v += __shfl_down_sync(0xffffffffu, v, o);
    return v;
}
__device__ __forceinline__ __half2 u2h(unsigned u){
    return *reinterpret_cast<__half2*>(&u);
}
__device__ __forceinline__ float lowf(unsigned u){
    return __half2float(__low2half(u2h(u)));
}

// Fused precompute: one block per row a, thread = column b.
__global__ void __launch_bounds__(NN) k_pre(const float* __restrict__ x){
    __shared__ float xa[DD];
    __shared__ float sa_sh;
    __shared__ float red[3][10];
    int a = blockIdx.x, b = threadIdx.x;
    if (b < DD) xa[b] = x[a*DD + b];
    __syncthreads();
    const float4* xb = reinterpret_cast<const float4*>(x + b*DD);
    float g = 0.f, nb = 0.f;
#pragma unroll
    for (int i = 0; i < DD/4; i++){
        float4 v = xb[i];
        g  += xa[4*i]*v.x + xa[4*i+1]*v.y + xa[4*i+2]*v.z + xa[4*i+3]*v.w;
        nb += v.x*v.x + v.y*v.y + v.z*v.z + v.w*v.w;
    }
    if (b == a){ sa_sh = nb; d_sn[a] = nb; }
    __syncthreads();
    float sa = sa_sh;
    float dp = sqrtf(fmaxf(sa + nb - 2.f*g, 0.f));
    float dm = sqrtf(fmaxf(sa + nb + 2.f*g, 0.f));
    float dl = dm - dp;
    d_PD[a*NN + b] = __floats2half2_rn(dl, dp);

    int w = b >> 5, l = b & 31;
    float v0 = warpRed(dl);
    float v1 = warpRed(b > a ? dp : 0.f);
    float v2 = warpRed(g);
    if (l == 0){ red[0][w] = v0; red[1][w] = v1; red[2][w] = v2; }
    __syncthreads();
    if (b == 0){
        float s0 = 0.f, s1 = 0.f, s2 = 0.f;
#pragma unroll
        for (int i = 0; i < 10; i++){ s0 += red[0][i]; s1 += red[1][i]; s2 += red[2][i]; }
        d_RD[a]   = s0;
        d_rowC[a] = s1;
        d_qd[a]   = s2;
    }
}

// Main: 286 blocks = 143 perm-groups x 2 row-halves. Each block streams its
// 160 rows of (Delta,Dp) directly from L2 for 7 perms, no mid-loop barriers.
__global__ void __launch_bounds__(NN) k_main(const float* __restrict__ x,
                                             const int* __restrict__ ptype,
                                             const int* __restrict__ perms){
    __shared__ __align__(16) __half2 wts[NN][8];  // (beta, chi) per (index, perm); slot 7 pad
    __shared__ float sZp[5][PB][DD];              // s-vector slice partials
    __shared__ float red[PB*5][10];

    int t = threadIdx.x, bid = blockIdx.x;
    int gidx = bid >> 1, h = bid & 1;
    int w = t >> 5, l = t & 31;
    int fn = (ptype[t] == 0);

    // pad slot 7 (read as part of uint4, never used)
    wts[t][7] = __floats2half2_rn(0.f, 0.f);

    // Build masks: thread t scatters to its image index a (bijection => full coverage).
#pragma unroll
    for (int pp = 0; pp < PB; pp++){
        int pi = gidx*PB + pp;                // dataset 0 = identity
        int a  = (pi == 0) ? t : perms[(pi-1)*NN + t];
        int fa = (ptype[a] == 0);
        int u  = (a != t) && fn && fa;
        wts[a][pp] = __floats2half2_rn((float)u, (float)fn);
    }
    __syncthreads();

    // ---- Dense stream over this half's rows: 4 row-slices x 80 quad-cols ----
    int g = t % 80, sl = t / 80;
    int rowBase = h*HROWS + sl;
    const __half2* rp = d_PD + (size_t)rowBase*NN + 4*g;
    const __half2 hz = __float2half2_rn(0.f);
    __half2 acc[PB][4];
#pragma unroll
    for (int p = 0; p < PB; p++)
#pragma unroll
        for (int c = 0; c < 4; c++) acc[p][c] = hz;
    float bb[PB], bx[PB], xx[PB];
#pragma unroll
    for (int p = 0; p < PB; p++){ bb[p] = 0.f; bx[p] = 0.f; xx[p] = 0.f; }

#pragma unroll 10
    for (int i = 0; i < HROWS/4; i++){        // 40 rows per thread
        int a = rowBase + 4*i;
        uint4 v4 = *reinterpret_cast<const uint4*>(rp);
        rp += 4*NN;
        uint4 w0 = *reinterpret_cast<const uint4*>(&wts[a][0]);
        uint4 w1 = *reinterpret_cast<const uint4*>(&wts[a][4]);
        __half2 val[4] = { u2h(v4.x), u2h(v4.y), u2h(v4.z), u2h(v4.w) };
        __half2 wp[PB] = { u2h(w0.x), u2h(w0.y), u2h(w0.z), u2h(w0.w),
                           u2h(w1.x), u2h(w1.y), u2h(w1.z) };
#pragma unroll
        for (int p = 0; p < PB; p++)
#pragma unroll
            for (int c = 0; c < 4; c++)
                acc[p][c] = __hfma2(val[c], wp[p], acc[p][c]);

        // promote half accumulators to fp32 every 10 rows
        if ((i % 10) == 9){
#pragma unroll
            for (int c = 0; c < 4; c++){
                int col = 4*g + c;
                uint4 wc0 = *reinterpret_cast<const uint4*>(&wts[col][0]);
                uint4 wc1 = *reinterpret_cast<const uint4*>(&wts[col][4]);
                unsigned wcu[PB] = { wc0.x, wc0.y, wc0.z, wc0.w, wc1.x, wc1.y, wc1.z };
#pragma unroll
                for (int p = 0; p < PB; p++){
                    float2 f  = __half22float2(acc[p][c]);
                    float2 wv = __half22float2(u2h(wcu[p]));
                    bb[p] = fmaf(wv.x, f.x, bb[p]);   // beta-col * (beta-row . Delta)
                    bx[p] = fmaf(wv.y, f.x, bx[p]);   // chi-col  * (beta-row . Delta)
                    xx[p] = fmaf(wv.y, f.y, xx[p]);   // chi-col  * (chi-row . Dp)
                    acc[p][c] = hz;
                }
            }
        }
    }

    // ---- s_p = sum_{a in half} beta_p[a] x[a,:] (fp32 exact) ----
    {
        int d = t & 63, g5 = t >> 6;          // 5 row-slices of 64 dims
        float sacc[PB];
#pragma unroll
        for (int p = 0; p < PB; p++) sacc[p] = 0.f;
        int row = h*HROWS + g5;
        const float* xp = x + (size_t)row*DD + d;
#pragma unroll 4
        for (int i2 = 0; i2 < HROWS/5; i2++){ // 32 rows per thread
            float xv = *xp;
            uint4 w0 = *reinterpret_cast<const uint4*>(&wts[row][0]);
            uint4 w1 = *reinterpret_cast<const uint4*>(&wts[row][4]);
            sacc[0] = fmaf(lowf(w0.x), xv, sacc[0]);
            sacc[1] = fmaf(lowf(w0.y), xv, sacc[1]);
            sacc[2] = fmaf(lowf(w0.z), xv, sacc[2]);
            sacc[3] = fmaf(lowf(w0.w), xv, sacc[3]);
            sacc[4] = fmaf(lowf(w1.x), xv, sacc[4]);
            sacc[5] = fmaf(lowf(w1.y), xv, sacc[5]);
            sacc[6] = fmaf(lowf(w1.z), xv, sacc[6]);
            xp += 5*DD; row += 5;
        }
#pragma unroll
        for (int p = 0; p < PB; p++) sZp[g5][p][t & 63] = sacc[p];
    }

    // ---- E1 reductions (row-restricted lin/qs) ----
    float inHalf = (t >= h*HROWS && t < h*HROWS + HROWS) ? 1.f : 0.f;
    float rdv = inHalf * d_RD[t], qdv = inHalf * d_qd[t];
    uint4 wt0 = *reinterpret_cast<const uint4*>(&wts[t][0]);
    uint4 wt1 = *reinterpret_cast<const uint4*>(&wts[t][4]);
    unsigned wtu[PB] = { wt0.x, wt0.y, wt0.z, wt0.w, wt1.x, wt1.y, wt1.z };
#pragma unroll
    for (int p = 0; p < PB; p++){
        float b  = lowf(wtu[p]);
        float r0 = warpRed(bb[p]);
        float r1 = warpRed(bx[p]);
        float r2 = warpRed(xx[p]);
        float r3 = warpRed(b*rdv);   // LIN partial
        float r4 = warpRed(b*qdv);   // QS  partial
        if (l == 0){
            red[p*5+0][w] = r0; red[p*5+1][w] = r1; red[p*5+2][w] = r2;
            red[p*5+3][w] = r3; red[p*5+4][w] = r4;
        }
    }
    __syncthreads();

    // ---- Write partials to scratch ----
    if (t < PB*5){
        int p = t / 5, j = t - p*5;
        float s = 0.f;
#pragma unroll
        for (int i = 0; i < 10; i++) s += red[p*5+j][i];
        d_sc[gidx][h][p][j] = s;
    }
    if (t < DD){
#pragma unroll
        for (int p = 0; p < PB; p++){
            d_sZ[gidx][h][p][t] = sZp[0][p][t] + sZp[1][p][t] + sZp[2][p][t]
                                + sZp[3][p][t] + sZp[4][p][t];
        }
    }
}

// Combine: 8 blocks x 128 threads; thread -> one dataset.
__global__ void __launch_bounds__(128) k_fin(float* __restrict__ out){
    __shared__ float scal[3];
    __shared__ float redf[3][4];
    int t = threadIdx.x, w = t >> 5, l = t & 31;

    // Perm-independent scalars: CDP, S1, X1SQ (each block computes redundantly).
    float pc = 0.f, ps = 0.f, pq = 0.f;
    for (int i = t; i < NN; i += 128){
        pc += d_rowC[i]; ps += d_sn[i]; pq += d_qd[i];
    }
    pc = warpRed(pc); ps = warpRed(ps); pq = warpRed(pq);
    if (l == 0){ redf[0][w] = pc; redf[1][w] = ps; redf[2][w] = pq; }
    __syncthreads();
    if (t == 0){
        scal[0] = redf[0][0]+redf[0][1]+redf[0][2]+redf[0][3];
        scal[1] = redf[1][0]+redf[1][1]+redf[1][2]+redf[1][3];
        scal[2] = redf[2][0]+redf[2][1]+redf[2][2]+redf[2][3];
    }
    __syncthreads();

    int pi = blockIdx.x*128 + t;
    if (pi < NG*PB){
        int gp = pi / PB, pp = pi - gp*PB;
        float BB  = d_sc[gp][0][pp][0] + d_sc[gp][1][pp][0];
        float BX  = d_sc[gp][0][pp][1] + d_sc[gp][1][pp][1];
        float XX  = d_sc[gp][0][pp][2] + d_sc[gp][1][pp][2];
        float LIN = d_sc[gp][0][pp][3] + d_sc[gp][1][pp][3];
        float QS  = d_sc[gp][0][pp][4] + d_sc[gp][1][pp][4];
        float GG = 0.f;
#pragma unroll 8
        for (int d = 0; d < DD; d++){
            float s = d_sZ[gp][0][pp][d] + d_sZ[gp][1][pp][d];
            GG = fmaf(s, s, GG);
        }
        const float M = 51040.f;                    // 320*319/2
        float Sv  = scal[0] + LIN + BB - 2.f*BX - XX;
        float Z2  = scal[2] - 4.f*QS + 4.f*GG;      // ||X1 - 2 sum_B x||^2
        float Sv2 = 320.f * scal[1] - Z2;
        out[pi] = (Sv2 - Sv*Sv/M) / (M - 1.f);
    }
}

extern "C" void kernel_launch(void* const* d_in, const int* in_sizes, int n_in,
                              void* d_out, int out_size){
    const float* data  = (const float*)d_in[0];
    const int*   ptype = (const int*)d_in[3];
    const int*   perms = (const int*)d_in[4];
    float* out = (float*)d_out;
    k_pre <<<NN,     NN>>>(data);
    k_main<<<2*NG,   NN>>>(data, ptype, perms);
    k_fin <<<8,     128>>>(out);
}

// round 12
// speedup vs baseline: 1.5229x; 1.4275x over previous
#include <cuda_runtime.h>
#include <cuda_fp16.h>
#include <cstdint>

#define NN 320
#define DD 64
#define PB 7
#define NBLK 143     // 143*7 = 1001 datasets exactly

// Precomputed, perm-independent state. d_PD padded by 4 rows for the
// last-iteration prefetch (rows 320..323 loaded but never used).
__device__ __align__(16) __half2 d_PD[(NN+4)*NN]; // (Delta, Dp) packed
__device__ float d_RD[NN];      // row sums of Delta (fp32)
__device__ float d_rowC[NN];    // per-row sum of Dp over b>a (fp32)
__device__ float d_sn[NN];      // squared norms
__device__ float d_qd[NN];      // X1 . x_a = row sum of Gram

__device__ __forceinline__ float warpRed(float v){
#pragma unroll
    for (int o = 16; o > 0; o >>= 1) v += __shfl_down_sync(0xffffffffu, v, o);
    return v;
}
__device__ __forceinline__ __half2 u2h(unsigned u){
    return *reinterpret_cast<__half2*>(&u);
}
__device__ __forceinline__ float lowf(unsigned u){
    return __half2float(__low2half(u2h(u)));
}

// Fused precompute: one block per row a, thread = column b.
__global__ void __launch_bounds__(NN) k_pre(const float* __restrict__ x){
    __shared__ float xa[DD];
    __shared__ float sa_sh;
    __shared__ float red[3][10];
    int a = blockIdx.x, b = threadIdx.x;
    if (b < DD) xa[b] = x[a*DD + b];
    __syncthreads();
    const float4* xb = reinterpret_cast<const float4*>(x + b*DD);
    float g = 0.f, nb = 0.f;
#pragma unroll
    for (int i = 0; i < DD/4; i++){
        float4 v = xb[i];
        g  += xa[4*i]*v.x + xa[4*i+1]*v.y + xa[4*i+2]*v.z + xa[4*i+3]*v.w;
        nb += v.x*v.x + v.y*v.y + v.z*v.z + v.w*v.w;
    }
    if (b == a){ sa_sh = nb; d_sn[a] = nb; }
    __syncthreads();
    float sa = sa_sh;
    float dp = sqrtf(fmaxf(sa + nb - 2.f*g, 0.f));
    float dm = sqrtf(fmaxf(sa + nb + 2.f*g, 0.f));
    float dl = dm - dp;
    d_PD[a*NN + b] = __floats2half2_rn(dl, dp);

    int w = b >> 5, l = b & 31;
    float v0 = warpRed(dl);
    float v1 = warpRed(b > a ? dp : 0.f);
    float v2 = warpRed(g);
    if (l == 0){ red[0][w] = v0; red[1][w] = v1; red[2][w] = v2; }
    __syncthreads();
    if (b == 0){
        float s0 = 0.f, s1 = 0.f, s2 = 0.f;
#pragma unroll
        for (int i = 0; i < 10; i++){ s0 += red[0][i]; s1 += red[1][i]; s2 += red[2][i]; }
        d_RD[a]   = s0;
        d_rowC[a] = s1;
        d_qd[a]   = s2;
    }
}

// Main: one block per 7 datasets. Dense mask-streaming, register-double-
// buffered LDG (prefetch next row-quad while computing current).
__global__ void __launch_bounds__(NN) k_main(const float* __restrict__ x,
                                             const int* __restrict__ ptype,
                                             const int* __restrict__ perms,
                                             float* __restrict__ out){
    __shared__ __align__(16) __half2 wts[NN][8];  // (beta, chi) per (index, perm); slot 7 pad
    __shared__ float sZp[5][PB][DD];              // s-vector slice partials
    __shared__ float red[PB*5+3][10];
    __shared__ float red2[PB][2];

    int t = threadIdx.x, bid = blockIdx.x;
    int w = t >> 5, l = t & 31;
    int fn = (ptype[t] == 0);

    // pad slot 7 (read as part of uint4, never used)
    wts[t][7] = __floats2half2_rn(0.f, 0.f);

    // Build masks: thread t scatters to its image index a (bijection => full coverage).
#pragma unroll
    for (int pp = 0; pp < PB; pp++){
        int pi = bid*PB + pp;                 // dataset 0 = identity
        int a  = (pi == 0) ? t : perms[(pi-1)*NN + t];
        int fa = (ptype[a] == 0);
        int u  = (a != t) && fn && fa;
        wts[a][pp] = __floats2half2_rn((float)u, (float)fn);
    }
    __syncthreads();

    // ---- Dense stream: rows a = sl + 4*i, thread covers cols 4g..4g+3 ----
    int g = t % 80, sl = t / 80;
    const __half2* rp = d_PD + (size_t)sl*NN + 4*g;
    const __half2 hz = __float2half2_rn(0.f);

    float bb[PB], bx[PB], xx[PB];
#pragma unroll
    for (int p = 0; p < PB; p++){ bb[p] = 0.f; bx[p] = 0.f; xx[p] = 0.f; }

    uint4 v_next = *reinterpret_cast<const uint4*>(rp);
    int i = 0;
#pragma unroll
    for (int ch = 0; ch < 3; ch++){
        int lim = (ch == 0) ? 27 : (ch == 1) ? 54 : 80;
        __half2 acc[PB][4];
#pragma unroll
        for (int p = 0; p < PB; p++)
#pragma unroll
            for (int c = 0; c < 4; c++) acc[p][c] = hz;
        for (; i < lim; i++){
            uint4 v4 = v_next;
            rp += 4*NN;
            v_next = *reinterpret_cast<const uint4*>(rp);   // prefetch (pad rows cover tail)
            int a = sl + 4*i;
            uint4 w0 = *reinterpret_cast<const uint4*>(&wts[a][0]);
            uint4 w1 = *reinterpret_cast<const uint4*>(&wts[a][4]);
            __half2 val[4] = { u2h(v4.x), u2h(v4.y), u2h(v4.z), u2h(v4.w) };
            __half2 wp[PB] = { u2h(w0.x), u2h(w0.y), u2h(w0.z), u2h(w0.w),
                               u2h(w1.x), u2h(w1.y), u2h(w1.z) };
#pragma unroll
            for (int p = 0; p < PB; p++)
#pragma unroll
                for (int c = 0; c < 4; c++)
                    acc[p][c] = __hfma2(val[c], wp[p], acc[p][c]);
        }
        // promote half accumulators to fp32 (3 chunks: 27/27/26 rows)
#pragma unroll
        for (int c = 0; c < 4; c++){
            int col = 4*g + c;
            uint4 wc0 = *reinterpret_cast<const uint4*>(&wts[col][0]);
            uint4 wc1 = *reinterpret_cast<const uint4*>(&wts[col][4]);
            unsigned wcu[PB] = { wc0.x, wc0.y, wc0.z, wc0.w, wc1.x, wc1.y, wc1.z };
#pragma unroll
            for (int p = 0; p < PB; p++){
                float2 f  = __half22float2(acc[p][c]);
                float2 wv = __half22float2(u2h(wcu[p]));
                bb[p] = fmaf(wv.x, f.x, bb[p]);   // beta-col * (beta-row . Delta)
                bx[p] = fmaf(wv.y, f.x, bx[p]);   // chi-col  * (beta-row . Delta)
                xx[p] = fmaf(wv.y, f.y, xx[p]);   // chi-col  * (chi-row . Dp)
            }
        }
    }

    // ---- s_p = sum_a beta_p[a] * x[a,:] (fp32 exact), 5 row-slices x 64 dims ----
    {
        int d = t & 63, g5 = t >> 6;
        float sacc[PB];
#pragma unroll
        for (int p = 0; p < PB; p++) sacc[p] = 0.f;
        const float* xp = x + (size_t)g5*DD + d;
        int row = g5;
#pragma unroll 4
        for (int i2 = 0; i2 < 64; i2++){
            float xv = *xp;
            uint4 w0 = *reinterpret_cast<const uint4*>(&wts[row][0]);
            uint4 w1 = *reinterpret_cast<const uint4*>(&wts[row][4]);
            sacc[0] = fmaf(lowf(w0.x), xv, sacc[0]);
            sacc[1] = fmaf(lowf(w0.y), xv, sacc[1]);
            sacc[2] = fmaf(lowf(w0.z), xv, sacc[2]);
            sacc[3] = fmaf(lowf(w0.w), xv, sacc[3]);
            sacc[4] = fmaf(lowf(w1.x), xv, sacc[4]);
            sacc[5] = fmaf(lowf(w1.y), xv, sacc[5]);
            sacc[6] = fmaf(lowf(w1.z), xv, sacc[6]);
            xp += 5*DD; row += 5;
        }
#pragma unroll
        for (int p = 0; p < PB; p++) sZp[g5][p][t & 63] = sacc[p];
    }

    // ---- E1 reductions ----
    float rdv = d_RD[t], qdv = d_qd[t];
    uint4 wt0 = *reinterpret_cast<const uint4*>(&wts[t][0]);
    uint4 wt1 = *reinterpret_cast<const uint4*>(&wts[t][4]);
    unsigned wtu[PB] = { wt0.x, wt0.y, wt0.z, wt0.w, wt1.x, wt1.y, wt1.z };
#pragma unroll
    for (int p = 0; p < PB; p++){
        float b  = lowf(wtu[p]);
        float r0 = warpRed(bb[p]);
        float r1 = warpRed(bx[p]);
        float r2 = warpRed(xx[p]);
        float r3 = warpRed(b*rdv);   // LIN = beta . RD
        float r4 = warpRed(b*qdv);   // QS  = beta . qd
        if (l == 0){
            red[p*5+0][w] = r0; red[p*5+1][w] = r1; red[p*5+2][w] = r2;
            red[p*5+3][w] = r3; red[p*5+4][w] = r4;
        }
    }
    {
        float rc = warpRed(d_rowC[t]);   // -> C_Dp
        float rs = warpRed(d_sn[t]);     // -> S1
        float rq = warpRed(qdv);         // -> ||X1||^2
        if (l == 0){ red[PB*5+0][w] = rc; red[PB*5+1][w] = rs; red[PB*5+2][w] = rq; }
    }
    __syncthreads();

    // ---- E2: GG_p = ||s_p||^2 ----
    if (t < DD){
#pragma unroll
        for (int p = 0; p < PB; p++){
            float s = sZp[0][p][t] + sZp[1][p][t] + sZp[2][p][t]
                    + sZp[3][p][t] + sZp[4][p][t];
            float r = warpRed(s*s);
            if (l == 0) red2[p][w] = r;   // warps 0,1
        }
    }
    __syncthreads();

    // ---- Final combine: one thread per perm ----
    if (t < PB){
        float BB=0.f, BX=0.f, XX=0.f, LIN=0.f, QS=0.f, CDP=0.f, S1=0.f, X1SQ=0.f;
#pragma unroll
        for (int i3 = 0; i3 < 10; i3++){
            BB  += red[t*5+0][i3]; BX += red[t*5+1][i3]; XX += red[t*5+2][i3];
            LIN += red[t*5+3][i3]; QS += red[t*5+4][i3];
            CDP += red[PB*5+0][i3]; S1 += red[PB*5+1][i3]; X1SQ += red[PB*5+2][i3];
        }
        float GG = red2[t][0] + red2[t][1];
        const float M = 51040.f;                    // 320*319/2
        float Sv  = CDP + LIN + BB - 2.f*BX - XX;
        float Z2  = X1SQ - 4.f*QS + 4.f*GG;         // ||X1 - 2 sum_B x||^2
        float Sv2 = 320.f * S1 - Z2;
        out[bid*PB + t] = (Sv2 - Sv*Sv/M) / (M - 1.f);
    }
}

extern "C" void kernel_launch(void* const* d_in, const int* in_sizes, int n_in,
                              void* d_out, int out_size){
    const float* data  = (const float*)d_in[0];
    const int*   ptype = (const int*)d_in[3];
    const int*   perms = (const int*)d_in[4];
    float* out = (float*)d_out;
    k_pre <<<NN,   NN>>>(data);
    k_main<<<NBLK, NN>>>(data, ptype, perms, out);
}

// round 13
// speedup vs baseline: 1.6025x; 1.0523x over previous
#include <cuda_runtime.h>
#include <cuda_fp16.h>
#include <cstdint>

#define NN 320
#define DD 64
#define PB 7
#define NBLK 143     // 143*7 = 1001 datasets exactly

// Precomputed, perm-independent state. d_PD padded by 20 rows: the depth-4
// prefetch ring reads up to row 335; padded values are never consumed.
__device__ __align__(16) __half2 d_PD[(NN+20)*NN]; // (Delta, Dp) packed
__device__ float d_RD[NN];      // row sums of Delta (fp32)
__device__ float d_rowC[NN];    // per-row sum of Dp over b>a (fp32)
__device__ float d_sn[NN];      // squared norms
__device__ float d_qd[NN];      // X1 . x_a = row sum of Gram

__device__ __forceinline__ float warpRed(float v){
#pragma unroll
    for (int o = 16; o > 0; o >>= 1) v += __shfl_down_sync(0xffffffffu, v, o);
    return v;
}
__device__ __forceinline__ __half2 u2h(unsigned u){
    return *reinterpret_cast<__half2*>(&u);
}
__device__ __forceinline__ float lowf(unsigned u){
    return __half2float(__low2half(u2h(u)));
}

// Fused precompute: one block per row a, thread = column b.
__global__ void __launch_bounds__(NN) k_pre(const float* __restrict__ x){
    __shared__ float xa[DD];
    __shared__ float sa_sh;
    __shared__ float red[3][10];
    int a = blockIdx.x, b = threadIdx.x;
    if (b < DD) xa[b] = x[a*DD + b];
    __syncthreads();
    const float4* xb = reinterpret_cast<const float4*>(x + b*DD);
    float g = 0.f, nb = 0.f;
#pragma unroll
    for (int i = 0; i < DD/4; i++){
        float4 v = xb[i];
        g  += xa[4*i]*v.x + xa[4*i+1]*v.y + xa[4*i+2]*v.z + xa[4*i+3]*v.w;
        nb += v.x*v.x + v.y*v.y + v.z*v.z + v.w*v.w;
    }
    if (b == a){ sa_sh = nb; d_sn[a] = nb; }
    __syncthreads();
    float sa = sa_sh;
    float dp = sqrtf(fmaxf(sa + nb - 2.f*g, 0.f));
    float dm = sqrtf(fmaxf(sa + nb + 2.f*g, 0.f));
    float dl = dm - dp;
    d_PD[a*NN + b] = __floats2half2_rn(dl, dp);

    int w = b >> 5, l = b & 31;
    float v0 = warpRed(dl);
    float v1 = warpRed(b > a ? dp : 0.f);
    float v2 = warpRed(g);
    if (l == 0){ red[0][w] = v0; red[1][w] = v1; red[2][w] = v2; }
    __syncthreads();
    if (b == 0){
        float s0 = 0.f, s1 = 0.f, s2 = 0.f;
#pragma unroll
        for (int i = 0; i < 10; i++){ s0 += red[0][i]; s1 += red[1][i]; s2 += red[2][i]; }
        d_RD[a]   = s0;
        d_rowC[a] = s1;
        d_qd[a]   = s2;
    }
}

// Main: one block per 7 datasets. Dense mask-streaming with a depth-4
// register prefetch ring (load->use gap = 4 iterations > L2 latency).
__global__ void __launch_bounds__(NN) k_main(const float* __restrict__ x,
                                             const int* __restrict__ ptype,
                                             const int* __restrict__ perms,
                                             float* __restrict__ out){
    __shared__ __align__(16) __half2 wts[NN][8];  // (beta, chi) per (index, perm); slot 7 pad
    __shared__ float sZp[5][PB][DD];              // s-vector slice partials
    __shared__ float red[PB*5+3][10];
    __shared__ float red2[PB][2];

    int t = threadIdx.x, bid = blockIdx.x;
    int w = t >> 5, l = t & 31;
    int fn = (ptype[t] == 0);

    // pad slot 7 (read as part of uint4, never used)
    wts[t][7] = __floats2half2_rn(0.f, 0.f);

    // Build masks: thread t scatters to its image index a (bijection => full coverage).
#pragma unroll
    for (int pp = 0; pp < PB; pp++){
        int pi = bid*PB + pp;                 // dataset 0 = identity
        int a  = (pi == 0) ? t : perms[(pi-1)*NN + t];
        int fa = (ptype[a] == 0);
        int u  = (a != t) && fn && fa;
        wts[a][pp] = __floats2half2_rn((float)u, (float)fn);
    }
    __syncthreads();

    // ---- Dense stream: rows a = sl + 4*i, thread covers cols 4g..4g+3 ----
    int g = t % 80, sl = t / 80;
    const __half2* rp = d_PD + (size_t)sl*NN + 4*g;
    const __half2 hz = __float2half2_rn(0.f);

    float bb[PB], bx[PB], xx[PB];
#pragma unroll
    for (int p = 0; p < PB; p++){ bb[p] = 0.f; bx[p] = 0.f; xx[p] = 0.f; }

    // Prefetch ring: rows sl, sl+4, sl+8, sl+12
    uint4 vb0 = *reinterpret_cast<const uint4*>(rp);
    uint4 vb1 = *reinterpret_cast<const uint4*>(rp +  4*NN);
    uint4 vb2 = *reinterpret_cast<const uint4*>(rp +  8*NN);
    uint4 vb3 = *reinterpret_cast<const uint4*>(rp + 12*NN);
    const __half2* rpf = rp + 16*NN;          // next row to prefetch

    int i = 0;
#pragma unroll
    for (int ch = 0; ch < 3; ch++){
        const int lim = (ch < 2) ? 28 : 24;   // 28+28+24 = 80 iterations
        __half2 acc[PB][4];
#pragma unroll
        for (int p = 0; p < PB; p++)
#pragma unroll
            for (int c = 0; c < 4; c++) acc[p][c] = hz;

        for (int ii = 0; ii < lim; ii += 4){
#pragma unroll
            for (int k = 0; k < 4; k++){
                uint4 v4 = (k==0) ? vb0 : (k==1) ? vb1 : (k==2) ? vb2 : vb3;
                // refill this slot 4 iterations ahead
                uint4 vnew = *reinterpret_cast<const uint4*>(rpf);
                rpf += 4*NN;
                if (k==0) vb0 = vnew; else if (k==1) vb1 = vnew;
                else if (k==2) vb2 = vnew; else vb3 = vnew;

                int a = sl + 4*(i + k);
                uint4 w0 = *reinterpret_cast<const uint4*>(&wts[a][0]);
                uint4 w1 = *reinterpret_cast<const uint4*>(&wts[a][4]);
                __half2 val[4] = { u2h(v4.x), u2h(v4.y), u2h(v4.z), u2h(v4.w) };
                __half2 wp[PB] = { u2h(w0.x), u2h(w0.y), u2h(w0.z), u2h(w0.w),
                                   u2h(w1.x), u2h(w1.y), u2h(w1.z) };
#pragma unroll
                for (int p = 0; p < PB; p++)
#pragma unroll
                    for (int c = 0; c < 4; c++)
                        acc[p][c] = __hfma2(val[c], wp[p], acc[p][c]);
            }
            i += 4;
        }

        // promote half accumulators to fp32 (chunks of 28/28/24 rows)
#pragma unroll
        for (int c = 0; c < 4; c++){
            int col = 4*g + c;
            uint4 wc0 = *reinterpret_cast<const uint4*>(&wts[col][0]);
            uint4 wc1 = *reinterpret_cast<const uint4*>(&wts[col][4]);
            unsigned wcu[PB] = { wc0.x, wc0.y, wc0.z, wc0.w, wc1.x, wc1.y, wc1.z };
#pragma unroll
            for (int p = 0; p < PB; p++){
                float2 f  = __half22float2(acc[p][c]);
                float2 wv = __half22float2(u2h(wcu[p]));
                bb[p] = fmaf(wv.x, f.x, bb[p]);   // beta-col * (beta-row . Delta)
                bx[p] = fmaf(wv.y, f.x, bx[p]);   // chi-col  * (beta-row . Delta)
                xx[p] = fmaf(wv.y, f.y, xx[p]);   // chi-col  * (chi-row . Dp)
            }
        }
    }

    // ---- s_p = sum_a beta_p[a] * x[a,:] (fp32 exact), 5 row-slices x 64 dims ----
    {
        int d = t & 63, g5 = t >> 6;
        float sacc[PB];
#pragma unroll
        for (int p = 0; p < PB; p++) sacc[p] = 0.f;
        const float* xp = x + (size_t)g5*DD + d;
        int row = g5;
#pragma unroll 4
        for (int i2 = 0; i2 < 64; i2++){
            float xv = *xp;
            uint4 w0 = *reinterpret_cast<const uint4*>(&wts[row][0]);
            uint4 w1 = *reinterpret_cast<const uint4*>(&wts[row][4]);
            sacc[0] = fmaf(lowf(w0.x), xv, sacc[0]);
            sacc[1] = fmaf(lowf(w0.y), xv, sacc[1]);
            sacc[2] = fmaf(lowf(w0.z), xv, sacc[2]);
            sacc[3] = fmaf(lowf(w0.w), xv, sacc[3]);
            sacc[4] = fmaf(lowf(w1.x), xv, sacc[4]);
            sacc[5] = fmaf(lowf(w1.y), xv, sacc[5]);
            sacc[6] = fmaf(lowf(w1.z), xv, sacc[6]);
            xp += 5*DD; row += 5;
        }
#pragma unroll
        for (int p = 0; p < PB; p++) sZp[g5][p][t & 63] = sacc[p];
    }

    // ---- E1 reductions ----
    float rdv = d_RD[t], qdv = d_qd[t];
    uint4 wt0 = *reinterpret_cast<const uint4*>(&wts[t][0]);
    uint4 wt1 = *reinterpret_cast<const uint4*>(&wts[t][4]);
    unsigned wtu[PB] = { wt0.x, wt0.y, wt0.z, wt0.w, wt1.x, wt1.y, wt1.z };
#pragma unroll
    for (int p = 0; p < PB; p++){
        float b  = lowf(wtu[p]);
        float r0 = warpRed(bb[p]);
        float r1 = warpRed(bx[p]);
        float r2 = warpRed(xx[p]);
        float r3 = warpRed(b*rdv);   // LIN = beta . RD
        float r4 = warpRed(b*qdv);   // QS  = beta . qd
        if (l == 0){
            red[p*5+0][w] = r0; red[p*5+1][w] = r1; red[p*5+2][w] = r2;
            red[p*5+3][w] = r3; red[p*5+4][w] = r4;
        }
    }
    {
        float rc = warpRed(d_rowC[t]);   // -> C_Dp
        float rs = warpRed(d_sn[t]);     // -> S1
        float rq = warpRed(qdv);         // -> ||X1||^2
        if (l == 0){ red[PB*5+0][w] = rc; red[PB*5+1][w] = rs; red[PB*5+2][w] = rq; }
    }
    __syncthreads();

    // ---- E2: GG_p = ||s_p||^2 ----
    if (t < DD){
#pragma unroll
        for (int p = 0; p < PB; p++){
            float s = sZp[0][p][t] + sZp[1][p][t] + sZp[2][p][t]
                    + sZp[3][p][t] + sZp[4][p][t];
            float r = warpRed(s*s);
            if (l == 0) red2[p][w] = r;   // warps 0,1
        }
    }
    __syncthreads();

    // ---- Final combine: one thread per perm ----
    if (t < PB){
        float BB=0.f, BX=0.f, XX=0.f, LIN=0.f, QS=0.f, CDP=0.f, S1=0.f, X1SQ=0.f;
#pragma unroll
        for (int i3 = 0; i3 < 10; i3++){
            BB  += red[t*5+0][i3]; BX += red[t*5+1][i3]; XX += red[t*5+2][i3];
            LIN += red[t*5+3][i3]; QS += red[t*5+4][i3];
            CDP += red[PB*5+0][i3]; S1 += red[PB*5+1][i3]; X1SQ += red[PB*5+2][i3];
        }
        float GG = red2[t][0] + red2[t][1];
        const float M = 51040.f;                    // 320*319/2
        float Sv  = CDP + LIN + BB - 2.f*BX - XX;
        float Z2  = X1SQ - 4.f*QS + 4.f*GG;         // ||X1 - 2 sum_B x||^2
        float Sv2 = 320.f * S1 - Z2;
        out[bid*PB + t] = (Sv2 - Sv*Sv/M) / (M - 1.f);
    }
}

extern "C" void kernel_launch(void* const* d_in, const int* in_sizes, int n_in,
                              void* d_out, int out_size){
    const float* data  = (const float*)d_in[0];
    const int*   ptype = (const int*)d_in[3];
    const int*   perms = (const int*)d_in[4];
    float* out = (float*)d_out;
    k_pre <<<NN,   NN>>>(data);
    k_main<<<NBLK, NN>>>(data, ptype, perms, out);
}

// round 14
// speedup vs baseline: 1.8422x; 1.1496x over previous
#include <cuda_runtime.h>
#include <cuda_fp16.h>
#include <cstdint>

#define NN 320
#define DD 64
#define NP 1001
#define NPAD 1024          // padded perm count (GEMM N dim)
#define MA 384             // A rows: 320 Delta + 64 x^T
#define NB1 96             // gemm1 blocks: (384/64)*(1024/64) = 6*16
#define NB2 80             // gemm2 blocks: (320/64)*(1024/64) = 5*16

// Static device state (no allocation).
__device__ __align__(16) __half d_A  [MA*NN];      // rows 0-319: Delta; 320-383: x^T
__device__ __align__(16) __half d_Dp2[NN*NN];      // Dp
__device__ __align__(16) __half d_Bb [NPAD*NN];    // beta masks, n-major
__device__ __align__(16) __half d_Bx [NPAD*NN];    // chi masks, n-major
__device__ __align__(16) float  d_C1 [NPAD*MA];    // C1[n][m] = (A . Bb)^T
__device__ __align__(16) float  d_C2 [NPAD*MA];    // C2[n][m] = (Dp . Bx)^T (m<320 valid)
__device__ float d_RD[NN];      // row sums of Delta
__device__ float d_rowC[NN];    // per-row sum of Dp over b>a
__device__ float d_sn[NN];      // squared norms
__device__ float d_qd[NN];      // X1 . x_a

__device__ __forceinline__ float warpRed(float v){
#pragma unroll
    for (int o = 16; o > 0; o >>= 1) v += __shfl_down_sync(0xffffffffu, v, o);
    return v;
}

// k_pre: blocks 0-319 build Delta/Dp rows + stats; blocks 320-383 build x^T rows.
__global__ void __launch_bounds__(NN) k_pre(const float* __restrict__ x){
    __shared__ float xa[DD];
    __shared__ float sa_sh;
    __shared__ float red[3][10];
    int a = blockIdx.x, b = threadIdx.x;
    if (a >= NN){                       // x^T rows: A[320+d][k] = x[k][d]
        int d = a - NN;
        d_A[(size_t)a*NN + b] = __float2half_rn(x[b*DD + d]);
        return;
    }
    if (b < DD) xa[b] = x[a*DD + b];
    __syncthreads();
    const float4* xb = reinterpret_cast<const float4*>(x + b*DD);
    float g = 0.f, nb = 0.f;
#pragma unroll
    for (int i = 0; i < DD/4; i++){
        float4 v = xb[i];
        g  += xa[4*i]*v.x + xa[4*i+1]*v.y + xa[4*i+2]*v.z + xa[4*i+3]*v.w;
        nb += v.x*v.x + v.y*v.y + v.z*v.z + v.w*v.w;
    }
    if (b == a){ sa_sh = nb; d_sn[a] = nb; }
    __syncthreads();
    float sa = sa_sh;
    float dp = sqrtf(fmaxf(sa + nb - 2.f*g, 0.f));
    float dm = sqrtf(fmaxf(sa + nb + 2.f*g, 0.f));
    float dl = dm - dp;
    d_A  [(size_t)a*NN + b] = __float2half_rn(dl);
    d_Dp2[(size_t)a*NN + b] = __float2half_rn(dp);

    int w = b >> 5, l = b & 31;
    float v0 = warpRed(dl);
    float v1 = warpRed(b > a ? dp : 0.f);
    float v2 = warpRed(g);
    if (l == 0){ red[0][w] = v0; red[1][w] = v1; red[2][w] = v2; }
    __syncthreads();
    if (b == 0){
        float s0 = 0.f, s1 = 0.f, s2 = 0.f;
#pragma unroll
        for (int i = 0; i < 10; i++){ s0 += red[0][i]; s1 += red[1][i]; s2 += red[2][i]; }
        d_RD[a]   = s0;
        d_rowC[a] = s1;
        d_qd[a]   = s2;
    }
}

// k_mask: one block per (padded) perm; scatter beta/chi into n-major mask rows.
__global__ void __launch_bounds__(NN) k_mask(const int* __restrict__ ptype,
                                             const int* __restrict__ perms){
    int p = blockIdx.x, t = threadIdx.x;
    if (p >= NP){
        d_Bb[(size_t)p*NN + t] = __float2half_rn(0.f);
        d_Bx[(size_t)p*NN + t] = __float2half_rn(0.f);
        return;
    }
    int a  = (p == 0) ? t : perms[(p-1)*NN + t];
    int fn = (ptype[t] == 0);
    int fa = (ptype[a] == 0);
    int u  = (a != t) && fn && fa;
    d_Bb[(size_t)p*NN + a] = __float2half_rn((float)u);
    d_Bx[(size_t)p*NN + a] = __float2half_rn((float)fn);
}

// k_gemm: C^T[n][m] = A[m][k] * B[n][k] via mma.sync m16n8k16 (f16 in, f32 accum).
// Blocks 0..95: A=d_A (M=384), B=d_Bb, C=d_C1. Blocks 96..175: d_Dp2/d_Bx/d_C2.
__global__ void __launch_bounds__(128) k_gemm(){
    __shared__ __align__(16) __half At[64][72];
    __shared__ __align__(16) __half Bt[64][72];
    int bid = blockIdx.x;
    const __half *Ag, *Bg; float* Cg; int tm, tn;
    if (bid < NB1){ Ag = d_A;   Bg = d_Bb; Cg = d_C1; tm = bid/16;        tn = bid%16; }
    else          { Ag = d_Dp2; Bg = d_Bx; Cg = d_C2; tm = (bid-NB1)/16;  tn = (bid-NB1)%16; }
    int m0 = tm*64, n0 = tn*64;
    int tid = threadIdx.x, lane = tid & 31, w = tid >> 5;

    float acc[8][4];
#pragma unroll
    for (int i = 0; i < 8; i++)
#pragma unroll
        for (int j = 0; j < 4; j++) acc[i][j] = 0.f;

    int r   = lane >> 2;          // 0..7
    int klo = (lane & 3) * 2;     // 0,2,4,6

    for (int kk = 0; kk < NN; kk += 64){
        // stage 64x64 half tiles (8 uint4 per row)
#pragma unroll
        for (int j = 0; j < 4; j++){
            int idx = tid + 128*j;
            int rr = idx >> 3, u = idx & 7;
            *reinterpret_cast<uint4*>(&At[rr][u*8]) =
                *reinterpret_cast<const uint4*>(Ag + (size_t)(m0+rr)*NN + kk + u*8);
            *reinterpret_cast<uint4*>(&Bt[rr][u*8]) =
                *reinterpret_cast<const uint4*>(Bg + (size_t)(n0+rr)*NN + kk + u*8);
        }
        __syncthreads();
#pragma unroll
        for (int k16 = 0; k16 < 64; k16 += 16){
            unsigned a0 = *reinterpret_cast<const unsigned*>(&At[16*w + r    ][k16 + klo    ]);
            unsigned a1 = *reinterpret_cast<const unsigned*>(&At[16*w + r + 8][k16 + klo    ]);
            unsigned a2 = *reinterpret_cast<const unsigned*>(&At[16*w + r    ][k16 + klo + 8]);
            unsigned a3 = *reinterpret_cast<const unsigned*>(&At[16*w + r + 8][k16 + klo + 8]);
#pragma unroll
            for (int n8 = 0; n8 < 8; n8++){
                unsigned b0 = *reinterpret_cast<const unsigned*>(&Bt[n8*8 + r][k16 + klo    ]);
                unsigned b1 = *reinterpret_cast<const unsigned*>(&Bt[n8*8 + r][k16 + klo + 8]);
                asm volatile(
                    "mma.sync.aligned.m16n8k16.row.col.f32.f16.f16.f32 "
                    "{%0,%1,%2,%3}, {%4,%5,%6,%7}, {%8,%9}, {%0,%1,%2,%3};"
                    : "+f"(acc[n8][0]), "+f"(acc[n8][1]), "+f"(acc[n8][2]), "+f"(acc[n8][3])
                    : "r"(a0), "r"(a1), "r"(a2), "r"(a3), "r"(b0), "r"(b1));
            }
        }
        __syncthreads();
    }
    // epilogue: transposed store C^T[n][m]
    int cc = (lane & 3) * 2;
#pragma unroll
    for (int n8 = 0; n8 < 8; n8++){
        int n = n0 + n8*8 + cc;
        int m = m0 + 16*w + r;
        Cg[(size_t)n*MA + m]         = acc[n8][0];
        Cg[(size_t)(n+1)*MA + m]     = acc[n8][1];
        Cg[(size_t)n*MA + m + 8]     = acc[n8][2];
        Cg[(size_t)(n+1)*MA + m + 8] = acc[n8][3];
    }
}

// k_red: one block per perm; weighted dots + scalars + output.
__global__ void __launch_bounds__(NN) k_red(float* __restrict__ out){
    __shared__ float red[9][10];
    int p = blockIdx.x, t = threadIdx.x;
    int w = t >> 5, l = t & 31;

    float U  = d_C1[(size_t)p*MA + t];
    float V  = d_C2[(size_t)p*MA + t];
    float bh = __half2float(d_Bb[(size_t)p*NN + t]);
    float ch = __half2float(d_Bx[(size_t)p*NN + t]);
    float rd = d_RD[t], qd = d_qd[t];
    float sv = (t < DD) ? d_C1[(size_t)p*MA + NN + t] : 0.f;

    float r0 = warpRed(bh*U);        // bb = beta^T Delta beta
    float r1 = warpRed(ch*U);        // bx = chi^T Delta beta
    float r2 = warpRed(ch*V);        // xx = chi^T Dp chi
    float r3 = warpRed(bh*rd);       // LIN
    float r4 = warpRed(bh*qd);       // QS
    float r5 = warpRed(sv*sv);       // GG
    float r6 = warpRed(d_rowC[t]);   // C_Dp
    float r7 = warpRed(d_sn[t]);     // S1
    float r8 = warpRed(qd);          // ||X1||^2
    if (l == 0){ red[0][w]=r0; red[1][w]=r1; red[2][w]=r2; red[3][w]=r3;
                 red[4][w]=r4; red[5][w]=r5; red[6][w]=r6; red[7][w]=r7; red[8][w]=r8; }
    __syncthreads();
    if (t == 0){
        float s[9];
#pragma unroll
        for (int j = 0; j < 9; j++){
            float acc = 0.f;
#pragma unroll
            for (int i = 0; i < 10; i++) acc += red[j][i];
            s[j] = acc;
        }
        const float M = 51040.f;                    // 320*319/2
        float Sv  = s[6] + s[3] + s[0] - 2.f*s[1] - s[2];
        float Z2  = s[8] - 4.f*s[4] + 4.f*s[5];     // ||X1 - 2 sum_B x||^2
        float Sv2 = 320.f * s[7] - Z2;
        out[p] = (Sv2 - Sv*Sv/M) / (M - 1.f);
    }
}

extern "C" void kernel_launch(void* const* d_in, const int* in_sizes, int n_in,
                              void* d_out, int out_size){
    const float* data  = (const float*)d_in[0];
    const int*   ptype = (const int*)d_in[3];
    const int*   perms = (const int*)d_in[4];
    float* out = (float*)d_out;
    k_pre <<<MA,       NN>>>(data);
    k_mask<<<NPAD,     NN>>>(ptype, perms);
    k_gemm<<<NB1+NB2, 128>>>();
    k_red <<<NP,       NN>>>(out);
}

// round 16
// speedup vs baseline: 1.9974x; 1.0843x over previous
#include <cuda_runtime.h>
#include <cuda_fp16.h>
#include <cstdint>

#define NN 320
#define DD 64
#define NP 1001
#define NPAD 1024          // padded perm count (GEMM N dim)
#define MA 384             // A rows: 320 Delta + 64 x^T
#define NB1 96             // gemm1 blocks: (384/64)*(1024/64)
#define NB2 80             // gemm2 blocks: (320/64)*(1024/64)

// Static device state (no allocation).
__device__ __align__(16) __half d_A  [MA*NN];      // rows 0-319: Delta; 320-383: x^T
__device__ __align__(16) __half d_Dp2[NN*NN];      // Dp
__device__ __align__(16) __half d_Bb [NPAD*NN];    // beta masks, n-major
__device__ __align__(16) __half d_Bx [NPAD*NN];    // chi masks, n-major
__device__ __align__(16) float  d_C1 [NPAD*MA];    // C1[n][m] = (A . Bb)^T
__device__ __align__(16) float  d_C2 [NPAD*MA];    // C2[n][m] = (Dp . Bx)^T (m<320 valid)
__device__ float d_RD[NN];      // row sums of Delta
__device__ float d_rowC[NN];    // per-row sum of Dp over b>a
__device__ float d_sn[NN];      // squared norms
__device__ float d_qd[NN];      // X1 . x_a

__device__ __forceinline__ float warpRed(float v){
#pragma unroll
    for (int o = 16; o > 0; o >>= 1) v += __shfl_down_sync(0xffffffffu, v, o);
    return v;
}

// k_pm: grid 1024. Every block scatters masks for perm p (verbatim k_mask);
// blocks <320 also build Delta/Dp rows + stats, 320-383 build x^T rows
// (verbatim k_pre). All branches are block-uniform.
__global__ void __launch_bounds__(NN) k_pm(const float* __restrict__ x,
                                           const int* __restrict__ ptype,
                                           const int* __restrict__ perms){
    __shared__ float xa[DD];
    __shared__ float sa_sh;
    __shared__ float red[3][10];
    int p = blockIdx.x, t = threadIdx.x;

    // ---- mask scatter (bijection => full coverage) ----
    if (p < NP){
        int ai = (p == 0) ? t : perms[(p-1)*NN + t];
        int fn = (ptype[t] == 0);
        int fa = (ptype[ai] == 0);
        int u  = (ai != t) && fn && fa;
        d_Bb[(size_t)p*NN + ai] = __float2half_rn((float)u);
        d_Bx[(size_t)p*NN + ai] = __float2half_rn((float)fn);
    } else {
        d_Bb[(size_t)p*NN + t] = __float2half_rn(0.f);
        d_Bx[(size_t)p*NN + t] = __float2half_rn(0.f);
    }
    if (p >= MA) return;

    int a = p, b = t;
    if (a >= NN){                       // x^T rows: A[320+d][k] = x[k][d]
        int d = a - NN;
        d_A[(size_t)a*NN + b] = __float2half_rn(x[b*DD + d]);
        return;
    }
    // ---- Delta/Dp row a ----
    if (b < DD) xa[b] = x[a*DD + b];
    __syncthreads();
    const float4* xb = reinterpret_cast<const float4*>(x + b*DD);
    float g = 0.f, nb = 0.f;
#pragma unroll
    for (int i = 0; i < DD/4; i++){
        float4 v = xb[i];
        g  += xa[4*i]*v.x + xa[4*i+1]*v.y + xa[4*i+2]*v.z + xa[4*i+3]*v.w;
        nb += v.x*v.x + v.y*v.y + v.z*v.z + v.w*v.w;
    }
    if (b == a){ sa_sh = nb; d_sn[a] = nb; }
    __syncthreads();
    float sa = sa_sh;
    float dp = sqrtf(fmaxf(sa + nb - 2.f*g, 0.f));
    float dm = sqrtf(fmaxf(sa + nb + 2.f*g, 0.f));
    float dl = dm - dp;
    d_A  [(size_t)a*NN + b] = __float2half_rn(dl);
    d_Dp2[(size_t)a*NN + b] = __float2half_rn(dp);

    int w = b >> 5, l = b & 31;
    float v0 = warpRed(dl);
    float v1 = warpRed(b > a ? dp : 0.f);
    float v2 = warpRed(g);
    if (l == 0){ red[0][w] = v0; red[1][w] = v1; red[2][w] = v2; }
    __syncthreads();
    if (b == 0){
        float s0 = 0.f, s1 = 0.f, s2 = 0.f;
#pragma unroll
        for (int i = 0; i < 10; i++){ s0 += red[0][i]; s1 += red[1][i]; s2 += red[2][i]; }
        d_RD[a]   = s0;
        d_rowC[a] = s1;
        d_qd[a]   = s2;
    }
}

// k_gemm: C^T[n][m] = A[m][k] * B[n][k] via mma.sync m16n8k16 (f16 in, f32 accum).
// Blocks 0..95: A=d_A (M=384), B=d_Bb, C=d_C1. Blocks 96..175: d_Dp2/d_Bx/d_C2.
__global__ void __launch_bounds__(128) k_gemm(){
    __shared__ __align__(16) __half At[64][72];
    __shared__ __align__(16) __half Bt[64][72];
    int bid = blockIdx.x;
    const __half *Ag, *Bg; float* Cg; int tm, tn;
    if (bid < NB1){ Ag = d_A;   Bg = d_Bb; Cg = d_C1; tm = bid/16;        tn = bid%16; }
    else          { Ag = d_Dp2; Bg = d_Bx; Cg = d_C2; tm = (bid-NB1)/16;  tn = (bid-NB1)%16; }
    int m0 = tm*64, n0 = tn*64;
    int tid = threadIdx.x, lane = tid & 31, w = tid >> 5;

    float acc[8][4];
#pragma unroll
    for (int i = 0; i < 8; i++)
#pragma unroll
        for (int j = 0; j < 4; j++) acc[i][j] = 0.f;

    int r   = lane >> 2;          // 0..7
    int klo = (lane & 3) * 2;     // 0,2,4,6

    for (int kk = 0; kk < NN; kk += 64){
#pragma unroll
        for (int j = 0; j < 4; j++){
            int idx = tid + 128*j;
            int rr = idx >> 3, u = idx & 7;
            *reinterpret_cast<uint4*>(&At[rr][u*8]) =
                *reinterpret_cast<const uint4*>(Ag + (size_t)(m0+rr)*NN + kk + u*8);
            *reinterpret_cast<uint4*>(&Bt[rr][u*8]) =
                *reinterpret_cast<const uint4*>(Bg + (size_t)(n0+rr)*NN + kk + u*8);
        }
        __syncthreads();
#pragma unroll
        for (int k16 = 0; k16 < 64; k16 += 16){
            unsigned a0 = *reinterpret_cast<const unsigned*>(&At[16*w + r    ][k16 + klo    ]);
            unsigned a1 = *reinterpret_cast<const unsigned*>(&At[16*w + r + 8][k16 + klo    ]);
            unsigned a2 = *reinterpret_cast<const unsigned*>(&At[16*w + r    ][k16 + klo + 8]);
            unsigned a3 = *reinterpret_cast<const unsigned*>(&At[16*w + r + 8][k16 + klo + 8]);
#pragma unroll
            for (int n8 = 0; n8 < 8; n8++){
                unsigned b0 = *reinterpret_cast<const unsigned*>(&Bt[n8*8 + r][k16 + klo    ]);
                unsigned b1 = *reinterpret_cast<const unsigned*>(&Bt[n8*8 + r][k16 + klo + 8]);
                asm volatile(
                    "mma.sync.aligned.m16n8k16.row.col.f32.f16.f16.f32 "
                    "{%0,%1,%2,%3}, {%4,%5,%6,%7}, {%8,%9}, {%0,%1,%2,%3};"
                    : "+f"(acc[n8][0]), "+f"(acc[n8][1]), "+f"(acc[n8][2]), "+f"(acc[n8][3])
                    : "r"(a0), "r"(a1), "r"(a2), "r"(a3), "r"(b0), "r"(b1));
            }
        }
        __syncthreads();
    }
    // epilogue: transposed store C^T[n][m]
    int cc = (lane & 3) * 2;
#pragma unroll
    for (int n8 = 0; n8 < 8; n8++){
        int n = n0 + n8*8 + cc;
        int m = m0 + 16*w + r;
        Cg[(size_t)n*MA + m]         = acc[n8][0];
        Cg[(size_t)(n+1)*MA + m]     = acc[n8][1];
        Cg[(size_t)n*MA + m + 8]     = acc[n8][2];
        Cg[(size_t)(n+1)*MA + m + 8] = acc[n8][3];
    }
}

// k_red2: two perms per block (grid 501); per-perm math identical to the
// passing single-perm version, shared scalars reduced once.
__global__ void __launch_bounds__(NN) k_red2(float* __restrict__ out){
    __shared__ float red[15][10];
    int t = threadIdx.x, w = t >> 5, l = t & 31;
    int pa = blockIdx.x*2, pb = pa + 1;
    bool hasB = (pb < NP);

    float rd = d_RD[t], qd = d_qd[t];

    float Ua  = d_C1[(size_t)pa*MA + t];
    float Va  = d_C2[(size_t)pa*MA + t];
    float bha = __half2float(d_Bb[(size_t)pa*NN + t]);
    float cha = __half2float(d_Bx[(size_t)pa*NN + t]);
    float sva = (t < DD) ? d_C1[(size_t)pa*MA + NN + t] : 0.f;

    float Ub = 0.f, Vb = 0.f, bhb = 0.f, chb = 0.f, svb = 0.f;
    if (hasB){
        Ub  = d_C1[(size_t)pb*MA + t];
        Vb  = d_C2[(size_t)pb*MA + t];
        bhb = __half2float(d_Bb[(size_t)pb*NN + t]);
        chb = __half2float(d_Bx[(size_t)pb*NN + t]);
        svb = (t < DD) ? d_C1[(size_t)pb*MA + NN + t] : 0.f;
    }

    float r0  = warpRed(bha*Ua);        // bb_a
    float r1  = warpRed(cha*Ua);        // bx_a
    float r2  = warpRed(cha*Va);        // xx_a
    float r3  = warpRed(bha*rd);        // lin_a
    float r4  = warpRed(bha*qd);        // qs_a
    float r5  = warpRed(sva*sva);       // gg_a
    float r6  = warpRed(bhb*Ub);        // bb_b
    float r7  = warpRed(chb*Ub);        // bx_b
    float r8  = warpRed(chb*Vb);        // xx_b
    float r9  = warpRed(bhb*rd);        // lin_b
    float r10 = warpRed(bhb*qd);        // qs_b
    float r11 = warpRed(svb*svb);       // gg_b
    float r12 = warpRed(d_rowC[t]);     // C_Dp
    float r13 = warpRed(d_sn[t]);       // S1
    float r14 = warpRed(qd);            // ||X1||^2
    if (l == 0){
        red[0][w]=r0;  red[1][w]=r1;  red[2][w]=r2;  red[3][w]=r3;  red[4][w]=r4;
        red[5][w]=r5;  red[6][w]=r6;  red[7][w]=r7;  red[8][w]=r8;  red[9][w]=r9;
        red[10][w]=r10; red[11][w]=r11; red[12][w]=r12; red[13][w]=r13; red[14][w]=r14;
    }
    __syncthreads();
    if (t < 2){
        if (t == 1 && !hasB) return;
        int o = t*6;                     // 0 for perm A, 6 for perm B
        float BB=0.f, BX=0.f, XX=0.f, LIN=0.f, QS=0.f, GG=0.f,
              CDP=0.f, S1=0.f, X1SQ=0.f;
#pragma unroll
        for (int i = 0; i < 10; i++){
            BB  += red[o+0][i]; BX += red[o+1][i]; XX += red[o+2][i];
            LIN += red[o+3][i]; QS += red[o+4][i]; GG += red[o+5][i];
            CDP += red[12][i];  S1 += red[13][i];  X1SQ += red[14][i];
        }
        const float M = 51040.f;                    // 320*319/2
        float Sv  = CDP + LIN + BB - 2.f*BX - XX;
        float Z2  = X1SQ - 4.f*QS + 4.f*GG;         // ||X1 - 2 sum_B x||^2
        float Sv2 = 320.f * S1 - Z2;
        out[pa + t] = (Sv2 - Sv*Sv/M) / (M - 1.f);
    }
}

extern "C" void kernel_launch(void* const* d_in, const int* in_sizes, int n_in,
                              void* d_out, int out_size){
    const float* data  = (const float*)d_in[0];
    const int*   ptype = (const int*)d_in[3];
    const int*   perms = (const int*)d_in[4];
    float* out = (float*)d_out;
    k_pm  <<<NPAD,     NN>>>(data, ptype, perms);
    k_gemm<<<NB1+NB2, 128>>>();
    k_red2<<<501,      NN>>>(out);
}

// round 17
// speedup vs baseline: 2.2153x; 1.1091x over previous
#include <cuda_runtime.h>
#include <cuda_fp16.h>
#include <cstdint>

#define NN 320
#define DD 64
#define NP 1001
#define NPAD 1024          // padded perm count (GEMM N dim)
#define MA 384             // A rows: 320 Delta + 64 x^T
#define NB1 96             // gemm1 blocks: (384/64)*(1024/64)
#define NB2 80             // gemm2 blocks: (320/64)*(1024/64)

// Static device state (no allocation).
__device__ __align__(16) __half d_A  [MA*NN];      // rows 0-319: Delta; 320-383: x^T
__device__ __align__(16) __half d_Dp2[NN*NN];      // Dp
__device__ __align__(16) __half d_Bb [NPAD*NN];    // beta masks, n-major
__device__ __align__(16) __half d_Bx [NPAD*NN];    // chi masks, n-major
__device__ __align__(16) float  d_C1 [NPAD*MA];    // C1[n][m] = (A . Bb)^T
__device__ __align__(16) float  d_C2 [NPAD*MA];    // C2[n][m] = (Dp . Bx)^T (m<320 valid)
__device__ float d_RD[NN];      // row sums of Delta
__device__ float d_rowC[NN];    // per-row sum of Dp over b>a
__device__ float d_sn[NN];      // squared norms
__device__ float d_qd[NN];      // X1 . x_a

__device__ __forceinline__ float warpRed(float v){
#pragma unroll
    for (int o = 16; o > 0; o >>= 1) v += __shfl_down_sync(0xffffffffu, v, o);
    return v;
}

// k_pm: grid 1024. Every block scatters masks for perm p; blocks 0-79 build
// 4 Delta/Dp rows each (+stats); blocks 80-95 build 4 x^T rows each.
__global__ void __launch_bounds__(NN) k_pm(const float* __restrict__ x,
                                           const int* __restrict__ ptype,
                                           const int* __restrict__ perms){
    __shared__ float xa[4][DD];
    __shared__ float sa_sh[4];
    __shared__ float red[12][10];
    int p = blockIdx.x, t = threadIdx.x;

    // ---- mask scatter (bijection => full coverage) ----
    if (p < NP){
        int ai = (p == 0) ? t : perms[(p-1)*NN + t];
        int fn = (ptype[t] == 0);
        int fa = (ptype[ai] == 0);
        int u  = (ai != t) && fn && fa;
        d_Bb[(size_t)p*NN + ai] = __float2half_rn((float)u);
        d_Bx[(size_t)p*NN + ai] = __float2half_rn((float)fn);
    } else {
        d_Bb[(size_t)p*NN + t] = __float2half_rn(0.f);
        d_Bx[(size_t)p*NN + t] = __float2half_rn(0.f);
    }
    if (p >= 96) return;

    if (p >= 80){                       // x^T rows: d0 = (p-80)*4
        int d0 = (p - 80)*4;
        float4 v = *reinterpret_cast<const float4*>(x + t*DD + d0);
        d_A[(size_t)(NN + d0    )*NN + t] = __float2half_rn(v.x);
        d_A[(size_t)(NN + d0 + 1)*NN + t] = __float2half_rn(v.y);
        d_A[(size_t)(NN + d0 + 2)*NN + t] = __float2half_rn(v.z);
        d_A[(size_t)(NN + d0 + 3)*NN + t] = __float2half_rn(v.w);
        return;
    }

    // ---- heavy: Delta/Dp rows a0..a0+3 ----
    int a0 = p*4;
    if (t < 4*DD) xa[t >> 6][t & 63] = x[(a0 + (t >> 6))*DD + (t & 63)];
    __syncthreads();

    const float4* xb = reinterpret_cast<const float4*>(x + t*DD);
    float g0 = 0.f, g1 = 0.f, g2 = 0.f, g3 = 0.f, nb = 0.f;
#pragma unroll
    for (int i = 0; i < DD/4; i++){
        float4 v  = xb[i];
        float4 a0v = reinterpret_cast<const float4*>(xa[0])[i];
        float4 a1v = reinterpret_cast<const float4*>(xa[1])[i];
        float4 a2v = reinterpret_cast<const float4*>(xa[2])[i];
        float4 a3v = reinterpret_cast<const float4*>(xa[3])[i];
        g0 += a0v.x*v.x + a0v.y*v.y + a0v.z*v.z + a0v.w*v.w;
        g1 += a1v.x*v.x + a1v.y*v.y + a1v.z*v.z + a1v.w*v.w;
        g2 += a2v.x*v.x + a2v.y*v.y + a2v.z*v.z + a2v.w*v.w;
        g3 += a3v.x*v.x + a3v.y*v.y + a3v.z*v.z + a3v.w*v.w;
        nb += v.x*v.x + v.y*v.y + v.z*v.z + v.w*v.w;
    }
    if (t == a0)   { sa_sh[0] = nb; d_sn[t] = nb; }
    if (t == a0+1) { sa_sh[1] = nb; d_sn[t] = nb; }
    if (t == a0+2) { sa_sh[2] = nb; d_sn[t] = nb; }
    if (t == a0+3) { sa_sh[3] = nb; d_sn[t] = nb; }
    __syncthreads();

    int w = t >> 5, l = t & 31;
    float gj[4] = { g0, g1, g2, g3 };
#pragma unroll
    for (int j = 0; j < 4; j++){
        int a = a0 + j;
        float sa = sa_sh[j];
        float dp = sqrtf(fmaxf(sa + nb - 2.f*gj[j], 0.f));
        float dm = sqrtf(fmaxf(sa + nb + 2.f*gj[j], 0.f));
        float dl = dm - dp;
        d_A  [(size_t)a*NN + t] = __float2half_rn(dl);
        d_Dp2[(size_t)a*NN + t] = __float2half_rn(dp);
        float v0 = warpRed(dl);
        float v1 = warpRed(t > a ? dp : 0.f);
        float v2 = warpRed(gj[j]);
        if (l == 0){ red[3*j][w] = v0; red[3*j+1][w] = v1; red[3*j+2][w] = v2; }
    }
    __syncthreads();
    if (t < 4){
        float s0 = 0.f, s1 = 0.f, s2 = 0.f;
#pragma unroll
        for (int i = 0; i < 10; i++){
            s0 += red[3*t][i]; s1 += red[3*t+1][i]; s2 += red[3*t+2][i];
        }
        d_RD  [a0 + t] = s0;
        d_rowC[a0 + t] = s1;
        d_qd  [a0 + t] = s2;
    }
}

// k_gemm: C^T[n][m] = A[m][k] * B[n][k] via mma.sync m16n8k16 (f16 in, f32 accum).
__global__ void __launch_bounds__(128) k_gemm(){
    __shared__ __align__(16) __half At[64][72];
    __shared__ __align__(16) __half Bt[64][72];
    int bid = blockIdx.x;
    const __half *Ag, *Bg; float* Cg; int tm, tn;
    if (bid < NB1){ Ag = d_A;   Bg = d_Bb; Cg = d_C1; tm = bid/16;        tn = bid%16; }
    else          { Ag = d_Dp2; Bg = d_Bx; Cg = d_C2; tm = (bid-NB1)/16;  tn = (bid-NB1)%16; }
    int m0 = tm*64, n0 = tn*64;
    int tid = threadIdx.x, lane = tid & 31, w = tid >> 5;

    float acc[8][4];
#pragma unroll
    for (int i = 0; i < 8; i++)
#pragma unroll
        for (int j = 0; j < 4; j++) acc[i][j] = 0.f;

    int r   = lane >> 2;          // 0..7
    int klo = (lane & 3) * 2;     // 0,2,4,6

    for (int kk = 0; kk < NN; kk += 64){
#pragma unroll
        for (int j = 0; j < 4; j++){
            int idx = tid + 128*j;
            int rr = idx >> 3, u = idx & 7;
            *reinterpret_cast<uint4*>(&At[rr][u*8]) =
                *reinterpret_cast<const uint4*>(Ag + (size_t)(m0+rr)*NN + kk + u*8);
            *reinterpret_cast<uint4*>(&Bt[rr][u*8]) =
                *reinterpret_cast<const uint4*>(Bg + (size_t)(n0+rr)*NN + kk + u*8);
        }
        __syncthreads();
#pragma unroll
        for (int k16 = 0; k16 < 64; k16 += 16){
            unsigned a0 = *reinterpret_cast<const unsigned*>(&At[16*w + r    ][k16 + klo    ]);
            unsigned a1 = *reinterpret_cast<const unsigned*>(&At[16*w + r + 8][k16 + klo    ]);
            unsigned a2 = *reinterpret_cast<const unsigned*>(&At[16*w + r    ][k16 + klo + 8]);
            unsigned a3 = *reinterpret_cast<const unsigned*>(&At[16*w + r + 8][k16 + klo + 8]);
#pragma unroll
            for (int n8 = 0; n8 < 8; n8++){
                unsigned b0 = *reinterpret_cast<const unsigned*>(&Bt[n8*8 + r][k16 + klo    ]);
                unsigned b1 = *reinterpret_cast<const unsigned*>(&Bt[n8*8 + r][k16 + klo + 8]);
                asm volatile(
                    "mma.sync.aligned.m16n8k16.row.col.f32.f16.f16.f32 "
                    "{%0,%1,%2,%3}, {%4,%5,%6,%7}, {%8,%9}, {%0,%1,%2,%3};"
                    : "+f"(acc[n8][0]), "+f"(acc[n8][1]), "+f"(acc[n8][2]), "+f"(acc[n8][3])
                    : "r"(a0), "r"(a1), "r"(a2), "r"(a3), "r"(b0), "r"(b1));
            }
        }
        __syncthreads();
    }
    int cc = (lane & 3) * 2;
#pragma unroll
    for (int n8 = 0; n8 < 8; n8++){
        int n = n0 + n8*8 + cc;
        int m = m0 + 16*w + r;
        Cg[(size_t)n*MA + m]         = acc[n8][0];
        Cg[(size_t)(n+1)*MA + m]     = acc[n8][1];
        Cg[(size_t)n*MA + m + 8]     = acc[n8][2];
        Cg[(size_t)(n+1)*MA + m + 8] = acc[n8][3];
    }
}

// k_red4: four perms per block (grid 251); per-perm math identical.
__global__ void __launch_bounds__(NN) k_red4(float* __restrict__ out){
    __shared__ float red[27][10];
    int t = threadIdx.x, w = t >> 5, l = t & 31;
    int p0 = blockIdx.x*4;

    float rd = d_RD[t], qd = d_qd[t];
    float rc = d_rowC[t], snv = d_sn[t];

#pragma unroll
    for (int i = 0; i < 4; i++){
        int pi = p0 + i;
        int pl = (pi < NP) ? pi : 0;      // safe load; write guarded later
        float U  = d_C1[(size_t)pl*MA + t];
        float V  = d_C2[(size_t)pl*MA + t];
        float bh = __half2float(d_Bb[(size_t)pl*NN + t]);
        float ch = __half2float(d_Bx[(size_t)pl*NN + t]);
        float sv = (t < DD) ? d_C1[(size_t)pl*MA + NN + t] : 0.f;
        float r0 = warpRed(bh*U);         // bb
        float r1 = warpRed(ch*U);         // bx
        float r2 = warpRed(ch*V);         // xx
        float r3 = warpRed(bh*rd);        // lin
        float r4 = warpRed(bh*qd);        // qs
        float r5 = warpRed(sv*sv);        // gg
        if (l == 0){
            red[i*6+0][w] = r0; red[i*6+1][w] = r1; red[i*6+2][w] = r2;
            red[i*6+3][w] = r3; red[i*6+4][w] = r4; red[i*6+5][w] = r5;
        }
    }
    {
        float r24 = warpRed(rc);          // C_Dp
        float r25 = warpRed(snv);         // S1
        float r26 = warpRed(qd);          // ||X1||^2
        if (l == 0){ red[24][w] = r24; red[25][w] = r25; red[26][w] = r26; }
    }
    __syncthreads();
    if (t < 4){
        int pi = p0 + t;
        if (pi < NP){
            int o = t*6;
            float BB=0.f, BX=0.f, XX=0.f, LIN=0.f, QS=0.f, GG=0.f,
                  CDP=0.f, S1=0.f, X1SQ=0.f;
#pragma unroll
            for (int i = 0; i < 10; i++){
                BB  += red[o+0][i]; BX += red[o+1][i]; XX += red[o+2][i];
                LIN += red[o+3][i]; QS += red[o+4][i]; GG += red[o+5][i];
                CDP += red[24][i];  S1 += red[25][i];  X1SQ += red[26][i];
            }
            const float M = 51040.f;                    // 320*319/2
            float Sv  = CDP + LIN + BB - 2.f*BX - XX;
            float Z2  = X1SQ - 4.f*QS + 4.f*GG;         // ||X1 - 2 sum_B x||^2
            float Sv2 = 320.f * S1 - Z2;
            out[pi] = (Sv2 - Sv*Sv/M) / (M - 1.f);
        }
    }
}

extern "C" void kernel_launch(void* const* d_in, const int* in_sizes, int n_in,
                              void* d_out, int out_size){
    const float* data  = (const float*)d_in[0];
    const int*   ptype = (const int*)d_in[3];
    const int*   perms = (const int*)d_in[4];
    float* out = (float*)d_out;
    k_pm  <<<NPAD,     NN>>>(data, ptype, perms);
    k_gemm<<<NB1+NB2, 128>>>();
    k_red4<<<251,      NN>>>(out);
}